// round 14
// baseline (speedup 1.0000x reference)
#include <cuda_runtime.h>
#include <math.h>
#include <stdint.h>

#define N_ITEM 81920
#define E_INT 327680
#define N_TGT 2048
#define NUM_NODE 50000
#define DIM 256
#define KDIM 512
#define ALPHA 0.2f
#define NOUT 49999

// ---------------- scratch (device globals; no allocs allowed) ----------------
__device__ float g_hn[(size_t)N_ITEM * DIM];    // gathered item embeddings
__device__ float g_ft[(size_t)N_ITEM * DIM];    // attention-aggregated (fp32)
__device__ float g_den[N_ITEM];                 // softmax denominators
__device__ float g_sel[(size_t)N_TGT * DIM];    // select accumulator (fp32)
// tf32-rounded copies for mma.sync consumption
__device__ float g_embr[(size_t)NUM_NODE * DIM];
__device__ float g_ftr[(size_t)N_ITEM * DIM];
__device__ float g_selr[(size_t)N_TGT * DIM];
__device__ float g_qwr[DIM * KDIM];
__device__ float g_posr[200 * DIM];

__device__ __forceinline__ void red_add_v4(float* p, float4 v) {
    asm volatile("red.global.add.v4.f32 [%0], {%1,%2,%3,%4};"
                 :: "l"(p), "f"(v.x), "f"(v.y), "f"(v.z), "f"(v.w) : "memory");
}
__device__ __forceinline__ uint32_t s2u(const void* p) {
    uint32_t a;
    asm("{ .reg .u64 t; cvta.to.shared.u64 t, %1; cvt.u32.u64 %0, t; }"
        : "=r"(a) : "l"(p));
    return a;
}
__device__ __forceinline__ float tf32r(float x) {
    float r; asm("cvt.rna.tf32.f32 %0, %1;" : "=f"(r) : "f"(x)); return r;
}
__device__ __forceinline__ void f4tf32(float4& v) {
    v.x = tf32r(v.x); v.y = tf32r(v.y); v.z = tf32r(v.z); v.w = tf32r(v.w);
}
__device__ __forceinline__ void cp16(uint32_t s, const void* g) {
    asm volatile("cp.async.cg.shared.global [%0], [%1], 16;"
                 :: "r"(s), "l"(g) : "memory");
}
__device__ __forceinline__ void cp16z(uint32_t s, const void* g, uint32_t sz) {
    asm volatile("cp.async.cg.shared.global [%0], [%1], 16, %2;"
                 :: "r"(s), "l"(g), "r"(sz) : "memory");
}
#define CP_COMMIT() asm volatile("cp.async.commit_group;" ::: "memory")
#define CP_WAIT1() asm volatile("cp.async.wait_group 1;" ::: "memory")
#define CP_WAIT0() asm volatile("cp.async.wait_group 0;" ::: "memory")

__device__ __forceinline__ void mma_tf32(float* d, const uint32_t* a, const uint32_t* b) {
    asm volatile(
        "mma.sync.aligned.m16n8k8.row.col.f32.tf32.tf32.f32 "
        "{%0,%1,%2,%3}, {%4,%5,%6,%7}, {%8,%9}, {%0,%1,%2,%3};"
        : "+f"(d[0]), "+f"(d[1]), "+f"(d[2]), "+f"(d[3])
        : "r"(a[0]), "r"(a[1]), "r"(a[2]), "r"(a[3]), "r"(b[0]), "r"(b[1]));
}

// ---------------- K0: zero accumulators ----------------
__global__ void k_zero() {
    int t = blockIdx.x * blockDim.x + threadIdx.x;
    int stride = gridDim.x * blockDim.x;
    const int nft = N_ITEM * DIM / 4;
    const int nsel = N_TGT * DIM / 4;
    float4 z = make_float4(0.f, 0.f, 0.f, 0.f);
    for (int i = t; i < nft; i += stride) ((float4*)g_ft)[i] = z;
    for (int i = t; i < nsel; i += stride) ((float4*)g_sel)[i] = z;
    for (int i = t; i < N_ITEM; i += stride) g_den[i] = 0.f;
}

// ---------------- K1: gather h_n = emb[iid] ----------------
__global__ void k_gather(const float* __restrict__ emb, const int* __restrict__ iid) {
    int t = blockIdx.x * blockDim.x + threadIdx.x;
    if (t >= N_ITEM * (DIM / 4)) return;
    int row = t >> 6;
    int c = t & 63;
    ((float4*)g_hn)[t] = ((const float4*)(emb + (size_t)iid[row] * DIM))[c];
}

// ---------------- rounding prep kernels ----------------
template <int DST>
__global__ void k_round_in(const float4* __restrict__ src, int n4) {
    int i = blockIdx.x * blockDim.x + threadIdx.x;
    if (i >= n4) return;
    float4 v = src[i];
    f4tf32(v);
    float4* d = (DST == 0) ? (float4*)g_embr : (DST == 1) ? (float4*)g_qwr
                                                          : (float4*)g_posr;
    d[i] = v;
}
__global__ void k_round_sel() {
    int i = blockIdx.x * blockDim.x + threadIdx.x;
    if (i >= N_TGT * (DIM / 4)) return;
    float4 v = ((const float4*)g_sel)[i];
    f4tf32(v);
    ((float4*)g_selr)[i] = v;
}

// ---------------- K2: fused edge attention + unnormalized scatter ------------
// warp per edge: logit -> exp; den[d] += ex; ft[d] += ex * hn[src] (src row is
// already resident in registers from the dot product). Division deferred.
__global__ void k_edge2(const int* __restrict__ i_src, const int* __restrict__ i_dst,
                        const float* __restrict__ p_w) {
    int e = blockIdx.x * 8 + (threadIdx.x >> 5);
    int lane = threadIdx.x & 31;
    int s = i_src[e], d = i_dst[e];
    const float4* sp = (const float4*)(g_hn + (size_t)s * DIM);
    const float4* dp = (const float4*)(g_hn + (size_t)d * DIM);
    const float4* wp = (const float4*)p_w;
    float4 a0 = sp[lane], a1 = sp[lane + 32];
    float4 b0 = dp[lane], b1 = dp[lane + 32];
    float4 w0 = __ldg(&wp[lane]), w1 = __ldg(&wp[lane + 32]);
    float acc = a0.x * b0.x * w0.x + a0.y * b0.y * w0.y
              + a0.z * b0.z * w0.z + a0.w * b0.w * w0.w
              + a1.x * b1.x * w1.x + a1.y * b1.y * w1.y
              + a1.z * b1.z * w1.z + a1.w * b1.w * w1.w;
#pragma unroll
    for (int o = 16; o; o >>= 1) acc += __shfl_xor_sync(0xffffffffu, acc, o);
    float l = acc > 0.f ? acc : ALPHA * acc;
    float ex = expf(l);
    if (lane == 0) atomicAdd(&g_den[d], ex);
    float* fp = g_ft + (size_t)d * DIM;
    a0.x *= ex; a0.y *= ex; a0.z *= ex; a0.w *= ex;
    a1.x *= ex; a1.y *= ex; a1.z *= ex; a1.w *= ex;
    red_add_v4(fp + lane * 4, a0);
    red_add_v4(fp + (lane + 32) * 4, a1);
}

// ---------------- K3: normalize ft by den; emit ft (fp32) + ftr (tf32) -------
__global__ void k_norm() {
    int i = blockIdx.x * blockDim.x + threadIdx.x;
    if (i >= N_ITEM * (DIM / 4)) return;
    int row = i >> 6;
    float inv = 1.f / fmaxf(__ldg(&g_den[row]), 1e-12f);
    float4 v = ((const float4*)g_ft)[i];
    v.x *= inv; v.y *= inv; v.z *= inv; v.w *= inv;
    ((float4*)g_ft)[i] = v;
    f4tf32(v);
    ((float4*)g_ftr)[i] = v;
}

// ---------------- K4: mid GEMM (mma.sync tf32) + tanh/coef/scatter ----------
// C[128,256] per CTA = X[128,512] @ q_w^T. 512 threads = 16 warps:
// wm=wid&3 (32 rows), wn=wid>>2 (64 cols). Warp tile 32x64: 2 m16 x 8 n8.
__global__ __launch_bounds__(512) void k_mid_mma(
    const int* __restrict__ pid, const int* __restrict__ agg_src,
    const int* __restrict__ agg_dst, const int* __restrict__ tid_arr,
    const float* __restrict__ tgt_emb) {
    extern __shared__ float sm[];
    float* Abuf[2] = {sm, sm + 4608};                 // 128*36 floats each
    float* Bbuf[2] = {sm + 9216, sm + 9216 + 9216};   // 256*36 floats each
    __shared__ int s_src[128], s_pid[128], s_dst[128], s_trow[128];
    __shared__ float s_coef[128];

    int tid = threadIdx.x, lane = tid & 31, wid = tid >> 5;
    int gid = lane >> 2, tig = lane & 3;
    int wm = wid & 3, wn = wid >> 2;
    int m0 = blockIdx.x * 128;

    if (tid < 128) {
        int r = m0 + tid;
        s_src[tid] = agg_src[r];
        s_pid[tid] = pid[r];
        int d = agg_dst[r];
        s_dst[tid] = d;
        s_trow[tid] = tid_arr[d];
        s_coef[tid] = 0.f;
    }
    __syncthreads();

    auto load_chunk = [&](int c, int b) {
        int k0 = c * 32;
#pragma unroll
        for (int it = 0; it < 2; it++) {
            int f = tid + 512 * it;
            int row = f >> 3, c4 = f & 7;
            const float* src = (k0 < DIM)
                ? g_ftr + (size_t)s_src[row] * DIM + k0 + c4 * 4
                : g_posr + (size_t)s_pid[row] * DIM + (k0 - DIM) + c4 * 4;
            cp16(s2u(&Abuf[b][row * 36 + c4 * 4]), src);
        }
#pragma unroll
        for (int it = 0; it < 4; it++) {
            int f = tid + 512 * it;
            int row = f >> 3, c4 = f & 7;
            cp16(s2u(&Bbuf[b][row * 36 + c4 * 4]),
                 g_qwr + (size_t)row * KDIM + k0 + c4 * 4);
        }
        CP_COMMIT();
    };

    float acc[2][8][4];
#pragma unroll
    for (int i = 0; i < 2; i++)
#pragma unroll
        for (int j = 0; j < 8; j++)
#pragma unroll
            for (int q = 0; q < 4; q++) acc[i][j][q] = 0.f;

    load_chunk(0, 0);
    for (int c = 0; c < 16; c++) {
        int b = c & 1;
        if (c + 1 < 16) { load_chunk(c + 1, b ^ 1); CP_WAIT1(); }
        else CP_WAIT0();
        __syncthreads();
        const float* A = Abuf[b];
        const float* B = Bbuf[b];
#pragma unroll
        for (int k8 = 0; k8 < 4; k8++) {
            int kk = k8 * 8 + tig;
            uint32_t aF[2][4];
#pragma unroll
            for (int mt = 0; mt < 2; mt++) {
                int r0 = wm * 32 + mt * 16 + gid;
                aF[mt][0] = __float_as_uint(A[r0 * 36 + kk]);
                aF[mt][1] = __float_as_uint(A[(r0 + 8) * 36 + kk]);
                aF[mt][2] = __float_as_uint(A[r0 * 36 + kk + 4]);
                aF[mt][3] = __float_as_uint(A[(r0 + 8) * 36 + kk + 4]);
            }
            uint32_t bF[8][2];
#pragma unroll
            for (int nt = 0; nt < 8; nt++) {
                int n = wn * 64 + nt * 8 + gid;
                bF[nt][0] = __float_as_uint(B[n * 36 + kk]);
                bF[nt][1] = __float_as_uint(B[n * 36 + kk + 4]);
            }
#pragma unroll
            for (int mt = 0; mt < 2; mt++)
#pragma unroll
                for (int nt = 0; nt < 8; nt++)
                    mma_tf32(acc[mt][nt], aF[mt], bF[nt]);
        }
        __syncthreads();
    }

    // coef partials: rows (wm*32+mt*16+gid, +8); cols (wn*64+nt*8+tig*2, +1)
    float p[4] = {0.f, 0.f, 0.f, 0.f};
#pragma unroll
    for (int mt = 0; mt < 2; mt++) {
        int r0 = wm * 32 + mt * 16 + gid;
        const float* tg0 = tgt_emb + (size_t)s_trow[r0] * DIM;
        const float* tg1 = tgt_emb + (size_t)s_trow[r0 + 8] * DIM;
#pragma unroll
        for (int nt = 0; nt < 8; nt++) {
            int n = wn * 64 + nt * 8 + tig * 2;
            p[mt * 2 + 0] += tanhf(acc[mt][nt][0]) * __ldg(&tg0[n])
                           + tanhf(acc[mt][nt][1]) * __ldg(&tg0[n + 1]);
            p[mt * 2 + 1] += tanhf(acc[mt][nt][2]) * __ldg(&tg1[n])
                           + tanhf(acc[mt][nt][3]) * __ldg(&tg1[n + 1]);
        }
    }
#pragma unroll
    for (int i = 0; i < 4; i++) {
        p[i] += __shfl_xor_sync(0xffffffffu, p[i], 1);
        p[i] += __shfl_xor_sync(0xffffffffu, p[i], 2);
    }
    if (tig == 0) {
        atomicAdd(&s_coef[wm * 32 + gid], p[0]);
        atomicAdd(&s_coef[wm * 32 + gid + 8], p[1]);
        atomicAdd(&s_coef[wm * 32 + 16 + gid], p[2]);
        atomicAdd(&s_coef[wm * 32 + 16 + gid + 8], p[3]);
    }
    __syncthreads();

    // scatter: select[dst] += coef * ft[src] (full-precision ft), 8 rows/warp
#pragma unroll
    for (int i = 0; i < 8; i++) {
        int rl = wid * 8 + i;
        float cf = s_coef[rl];
        const float4* fp = (const float4*)(g_ft + (size_t)s_src[rl] * DIM);
        float* op = g_sel + (size_t)s_dst[rl] * DIM;
#pragma unroll
        for (int j = 0; j < 2; j++) {
            int cc = lane + 32 * j;
            float4 v = fp[cc];
            v.x *= cf; v.y *= cf; v.z *= cf; v.w *= cf;
            red_add_v4(op + cc * 4, v);
        }
    }
}

// ---------------- K5: scores = selr @ embr[1:]^T (mma.sync tf32) ------------
// 256x128 block tile, 512 threads = 16 warps: wm=wid&7 (32 rows), wn=wid>>3
// (64 cols). Warp tile 32x64.
__global__ __launch_bounds__(512) void k_scores_mma(float* __restrict__ out) {
    extern __shared__ float sm[];
    float* Abuf[2] = {sm, sm + 9216};                 // 256*36 floats each
    float* Bbuf[2] = {sm + 18432, sm + 18432 + 4608}; // 128*36 floats each
    int tid = threadIdx.x, lane = tid & 31, wid = tid >> 5;
    int gid = lane >> 2, tig = lane & 3;
    int wm = wid & 7, wn = wid >> 3;
    int n0 = blockIdx.x * 128, m0 = blockIdx.y * 256;

    auto load_chunk = [&](int c, int b) {
        int k0 = c * 32;
#pragma unroll
        for (int it = 0; it < 4; it++) {
            int f = tid + 512 * it;
            int row = f >> 3, c4 = f & 7;
            cp16(s2u(&Abuf[b][row * 36 + c4 * 4]),
                 g_selr + (size_t)(m0 + row) * DIM + k0 + c4 * 4);
        }
#pragma unroll
        for (int it = 0; it < 2; it++) {
            int f = tid + 512 * it;
            int row = f >> 3, c4 = f & 7;
            int gn = n0 + row;
            uint32_t ok = (gn < NOUT) ? 16u : 0u;
            const float* src = g_embr + (size_t)((gn < NOUT) ? gn + 1 : 0) * DIM
                             + k0 + c4 * 4;
            cp16z(s2u(&Bbuf[b][row * 36 + c4 * 4]), src, ok);
        }
        CP_COMMIT();
    };

    float acc[2][8][4];
#pragma unroll
    for (int i = 0; i < 2; i++)
#pragma unroll
        for (int j = 0; j < 8; j++)
#pragma unroll
            for (int q = 0; q < 4; q++) acc[i][j][q] = 0.f;

    load_chunk(0, 0);
    for (int c = 0; c < 8; c++) {
        int b = c & 1;
        if (c + 1 < 8) { load_chunk(c + 1, b ^ 1); CP_WAIT1(); }
        else CP_WAIT0();
        __syncthreads();
        const float* A = Abuf[b];
        const float* B = Bbuf[b];
#pragma unroll
        for (int k8 = 0; k8 < 4; k8++) {
            int kk = k8 * 8 + tig;
            uint32_t aF[2][4];
#pragma unroll
            for (int mt = 0; mt < 2; mt++) {
                int r0 = wm * 32 + mt * 16 + gid;
                aF[mt][0] = __float_as_uint(A[r0 * 36 + kk]);
                aF[mt][1] = __float_as_uint(A[(r0 + 8) * 36 + kk]);
                aF[mt][2] = __float_as_uint(A[r0 * 36 + kk + 4]);
                aF[mt][3] = __float_as_uint(A[(r0 + 8) * 36 + kk + 4]);
            }
            uint32_t bF[8][2];
#pragma unroll
            for (int nt = 0; nt < 8; nt++) {
                int n = wn * 64 + nt * 8 + gid;
                bF[nt][0] = __float_as_uint(B[n * 36 + kk]);
                bF[nt][1] = __float_as_uint(B[n * 36 + kk + 4]);
            }
#pragma unroll
            for (int mt = 0; mt < 2; mt++)
#pragma unroll
                for (int nt = 0; nt < 8; nt++)
                    mma_tf32(acc[mt][nt], aF[mt], bF[nt]);
        }
        __syncthreads();
    }

    // epilogue: direct STG from fragments
#pragma unroll
    for (int mt = 0; mt < 2; mt++) {
        int r0 = m0 + wm * 32 + mt * 16 + gid;
#pragma unroll
        for (int nt = 0; nt < 8; nt++) {
            int n = n0 + wn * 64 + nt * 8 + tig * 2;
            if (n < NOUT) {
                out[(size_t)r0 * NOUT + n] = acc[mt][nt][0];
                out[(size_t)(r0 + 8) * NOUT + n] = acc[mt][nt][2];
                if (n + 1 < NOUT) {
                    out[(size_t)r0 * NOUT + n + 1] = acc[mt][nt][1];
                    out[(size_t)(r0 + 8) * NOUT + n + 1] = acc[mt][nt][3];
                }
            }
        }
    }
}

// ---------------- launch ----------------
extern "C" void kernel_launch(void* const* d_in, const int* in_sizes, int n_in,
                              void* d_out, int out_size) {
    const int* iid = (const int*)d_in[2];
    const int* pid = (const int*)d_in[3];
    const int* tid = (const int*)d_in[4];
    const int* i_src = (const int*)d_in[5];
    const int* i_dst = (const int*)d_in[6];
    const int* agg_src = (const int*)d_in[7];
    const int* agg_dst = (const int*)d_in[8];
    const float* emb = (const float*)d_in[9];
    const float* pos_emb = (const float*)d_in[10];
    const float* tgt_emb = (const float*)d_in[11];
    const float* p_w = (const float*)d_in[12];
    const float* q_w = (const float*)d_in[13];
    float* out = (float*)d_out;

    const int SMEM_GEMM = 110592;   // 27648 floats
    cudaFuncSetAttribute(k_mid_mma, cudaFuncAttributeMaxDynamicSharedMemorySize,
                         SMEM_GEMM);
    cudaFuncSetAttribute(k_scores_mma, cudaFuncAttributeMaxDynamicSharedMemorySize,
                         SMEM_GEMM);

    k_zero<<<2048, 256>>>();
    k_gather<<<(N_ITEM * (DIM / 4) + 255) / 256, 256>>>(emb, iid);
    k_round_in<0><<<(NUM_NODE * (DIM / 4) + 255) / 256, 256>>>(
        (const float4*)emb, NUM_NODE * (DIM / 4));
    k_round_in<1><<<(DIM * KDIM / 4 + 255) / 256, 256>>>(
        (const float4*)q_w, DIM * KDIM / 4);
    k_round_in<2><<<(200 * (DIM / 4) + 255) / 256, 256>>>(
        (const float4*)pos_emb, 200 * (DIM / 4));
    k_edge2<<<E_INT / 8, 256>>>(i_src, i_dst, p_w);
    k_norm<<<(N_ITEM * (DIM / 4) + 255) / 256, 256>>>();
    k_mid_mma<<<N_ITEM / 128, 512, SMEM_GEMM>>>(pid, agg_src, agg_dst, tid, tgt_emb);
    k_round_sel<<<(N_TGT * (DIM / 4) + 255) / 256, 256>>>();
    dim3 g5((NOUT + 127) / 128, N_TGT / 256);
    k_scores_mma<<<g5, 512, SMEM_GEMM>>>(out);
}

// round 15
// speedup vs baseline: 1.2264x; 1.2264x over previous
#include <cuda_runtime.h>
#include <math.h>
#include <stdint.h>

#define N_ITEM 81920
#define E_INT 327680
#define N_TGT 2048
#define NUM_NODE 50000
#define DIM 256
#define KDIM 512
#define ALPHA 0.2f
#define NOUT 49999

// ---------------- scratch (device globals; no allocs allowed) ----------------
__device__ float g_ft[(size_t)N_ITEM * DIM];    // attention-aggregated (fp32)
__device__ float g_den[N_ITEM];                 // softmax denominators
__device__ float g_sel[(size_t)N_TGT * DIM];    // select accumulator (fp32)
// tf32-rounded copies for mma.sync consumption
__device__ float g_embr[(size_t)NUM_NODE * DIM];
__device__ float g_ftr[(size_t)N_ITEM * DIM];
__device__ float g_selr[(size_t)N_TGT * DIM];
__device__ float g_qwr[DIM * KDIM];
__device__ float g_posr[200 * DIM];

__device__ __forceinline__ void red_add_v4(float* p, float4 v) {
    asm volatile("red.global.add.v4.f32 [%0], {%1,%2,%3,%4};"
                 :: "l"(p), "f"(v.x), "f"(v.y), "f"(v.z), "f"(v.w) : "memory");
}
__device__ __forceinline__ uint32_t s2u(const void* p) {
    uint32_t a;
    asm("{ .reg .u64 t; cvta.to.shared.u64 t, %1; cvt.u32.u64 %0, t; }"
        : "=r"(a) : "l"(p));
    return a;
}
__device__ __forceinline__ float tf32r(float x) {
    float r; asm("cvt.rna.tf32.f32 %0, %1;" : "=f"(r) : "f"(x)); return r;
}
__device__ __forceinline__ void f4tf32(float4& v) {
    v.x = tf32r(v.x); v.y = tf32r(v.y); v.z = tf32r(v.z); v.w = tf32r(v.w);
}
__device__ __forceinline__ void cp16(uint32_t s, const void* g) {
    asm volatile("cp.async.cg.shared.global [%0], [%1], 16;"
                 :: "r"(s), "l"(g) : "memory");
}
__device__ __forceinline__ void cp16z(uint32_t s, const void* g, uint32_t sz) {
    asm volatile("cp.async.cg.shared.global [%0], [%1], 16, %2;"
                 :: "r"(s), "l"(g), "r"(sz) : "memory");
}
#define CP_COMMIT() asm volatile("cp.async.commit_group;" ::: "memory")
#define CP_WAIT1() asm volatile("cp.async.wait_group 1;" ::: "memory")
#define CP_WAIT0() asm volatile("cp.async.wait_group 0;" ::: "memory")

__device__ __forceinline__ void mma_tf32(float* d, const uint32_t* a, const uint32_t* b) {
    asm volatile(
        "mma.sync.aligned.m16n8k8.row.col.f32.tf32.tf32.f32 "
        "{%0,%1,%2,%3}, {%4,%5,%6,%7}, {%8,%9}, {%0,%1,%2,%3};"
        : "+f"(d[0]), "+f"(d[1]), "+f"(d[2]), "+f"(d[3])
        : "r"(a[0]), "r"(a[1]), "r"(a[2]), "r"(a[3]), "r"(b[0]), "r"(b[1]));
}

// ---------------- K0: zero accumulators ----------------
__global__ void k_zero() {
    int t = blockIdx.x * blockDim.x + threadIdx.x;
    int stride = gridDim.x * blockDim.x;
    const int nft = N_ITEM * DIM / 4;
    const int nsel = N_TGT * DIM / 4;
    float4 z = make_float4(0.f, 0.f, 0.f, 0.f);
    for (int i = t; i < nft; i += stride) ((float4*)g_ft)[i] = z;
    for (int i = t; i < nsel; i += stride) ((float4*)g_sel)[i] = z;
    for (int i = t; i < N_ITEM; i += stride) g_den[i] = 0.f;
}

// ---------------- rounding prep kernels ----------------
template <int DST>
__global__ void k_round_in(const float4* __restrict__ src, int n4) {
    int i = blockIdx.x * blockDim.x + threadIdx.x;
    if (i >= n4) return;
    float4 v = src[i];
    f4tf32(v);
    float4* d = (DST == 0) ? (float4*)g_embr : (DST == 1) ? (float4*)g_qwr
                                                          : (float4*)g_posr;
    d[i] = v;
}
__global__ void k_round_sel() {
    int i = blockIdx.x * blockDim.x + threadIdx.x;
    if (i >= N_TGT * (DIM / 4)) return;
    float4 v = ((const float4*)g_sel)[i];
    f4tf32(v);
    ((float4*)g_selr)[i] = v;
}

// ---------------- K2: fused edge attention + unnormalized scatter ------------
// warp per edge; rows read directly from emb via iid (emb's 51 MB working set
// is L2-resident). logit -> exp; den[d] += ex; ft[d] += ex * emb[iid[src]].
// Softmax division deferred to k_norm.
__global__ void k_edge2(const int* __restrict__ i_src, const int* __restrict__ i_dst,
                        const int* __restrict__ iid, const float* __restrict__ emb,
                        const float* __restrict__ p_w) {
    int e = blockIdx.x * 8 + (threadIdx.x >> 5);
    int lane = threadIdx.x & 31;
    int s = i_src[e], d = i_dst[e];
    int si = __ldg(&iid[s]), di = __ldg(&iid[d]);
    const float4* sp = (const float4*)(emb + (size_t)si * DIM);
    const float4* dp = (const float4*)(emb + (size_t)di * DIM);
    const float4* wp = (const float4*)p_w;
    float4 a0 = __ldg(&sp[lane]), a1 = __ldg(&sp[lane + 32]);
    float4 b0 = __ldg(&dp[lane]), b1 = __ldg(&dp[lane + 32]);
    float4 w0 = __ldg(&wp[lane]), w1 = __ldg(&wp[lane + 32]);
    float acc = a0.x * b0.x * w0.x + a0.y * b0.y * w0.y
              + a0.z * b0.z * w0.z + a0.w * b0.w * w0.w
              + a1.x * b1.x * w1.x + a1.y * b1.y * w1.y
              + a1.z * b1.z * w1.z + a1.w * b1.w * w1.w;
#pragma unroll
    for (int o = 16; o; o >>= 1) acc += __shfl_xor_sync(0xffffffffu, acc, o);
    float l = acc > 0.f ? acc : ALPHA * acc;
    float ex = expf(l);
    if (lane == 0) atomicAdd(&g_den[d], ex);
    float* fp = g_ft + (size_t)d * DIM;
    a0.x *= ex; a0.y *= ex; a0.z *= ex; a0.w *= ex;
    a1.x *= ex; a1.y *= ex; a1.z *= ex; a1.w *= ex;
    red_add_v4(fp + lane * 4, a0);
    red_add_v4(fp + (lane + 32) * 4, a1);
}

// ---------------- K3: normalize ft by den; emit ft (fp32) + ftr (tf32) -------
__global__ void k_norm() {
    int i = blockIdx.x * blockDim.x + threadIdx.x;
    if (i >= N_ITEM * (DIM / 4)) return;
    int row = i >> 6;
    float inv = 1.f / fmaxf(__ldg(&g_den[row]), 1e-12f);
    float4 v = ((const float4*)g_ft)[i];
    v.x *= inv; v.y *= inv; v.z *= inv; v.w *= inv;
    ((float4*)g_ft)[i] = v;
    f4tf32(v);
    ((float4*)g_ftr)[i] = v;
}

// ---------------- K4: mid GEMM (mma.sync tf32) + tanh/coef/scatter ----------
// R9 geometry: C[64,256] per CTA, 256 threads = 8 warps, wm=wid&1, wn=wid>>1,
// warp tile 32x64 = 2 m16 x 8 n8, m16n8k8.
__global__ __launch_bounds__(256) void k_mid_mma(
    const int* __restrict__ pid, const int* __restrict__ agg_src,
    const int* __restrict__ agg_dst, const int* __restrict__ tid_arr,
    const float* __restrict__ tgt_emb) {
    extern __shared__ float sm[];
    float* Abuf[2] = {sm, sm + 2304};                 // 64*36 floats each
    float* Bbuf[2] = {sm + 4608, sm + 4608 + 9216};   // 256*36 floats each
    __shared__ int s_src[64], s_pid[64], s_dst[64], s_trow[64];
    __shared__ float s_coef[64];

    int tid = threadIdx.x, lane = tid & 31, wid = tid >> 5;
    int gid = lane >> 2, tig = lane & 3;
    int wm = wid & 1, wn = wid >> 1;
    int m0 = blockIdx.x * 64;

    if (tid < 64) {
        int r = m0 + tid;
        s_src[tid] = agg_src[r];
        s_pid[tid] = pid[r];
        int d = agg_dst[r];
        s_dst[tid] = d;
        s_trow[tid] = tid_arr[d];
        s_coef[tid] = 0.f;
    }
    __syncthreads();

    auto load_chunk = [&](int c, int b) {
        int k0 = c * 32;
#pragma unroll
        for (int it = 0; it < 2; it++) {
            int f = tid + 256 * it;
            int row = f >> 3, c4 = f & 7;
            const float* src = (k0 < DIM)
                ? g_ftr + (size_t)s_src[row] * DIM + k0 + c4 * 4
                : g_posr + (size_t)s_pid[row] * DIM + (k0 - DIM) + c4 * 4;
            cp16(s2u(&Abuf[b][row * 36 + c4 * 4]), src);
        }
#pragma unroll
        for (int it = 0; it < 8; it++) {
            int f = tid + 256 * it;
            int row = f >> 3, c4 = f & 7;
            cp16(s2u(&Bbuf[b][row * 36 + c4 * 4]),
                 g_qwr + (size_t)row * KDIM + k0 + c4 * 4);
        }
        CP_COMMIT();
    };

    float acc[2][8][4];
#pragma unroll
    for (int i = 0; i < 2; i++)
#pragma unroll
        for (int j = 0; j < 8; j++)
#pragma unroll
            for (int q = 0; q < 4; q++) acc[i][j][q] = 0.f;

    load_chunk(0, 0);
    for (int c = 0; c < 16; c++) {
        int b = c & 1;
        if (c + 1 < 16) { load_chunk(c + 1, b ^ 1); CP_WAIT1(); }
        else CP_WAIT0();
        __syncthreads();
        const float* A = Abuf[b];
        const float* B = Bbuf[b];
#pragma unroll
        for (int k8 = 0; k8 < 4; k8++) {
            int kk = k8 * 8 + tig;
            uint32_t aF[2][4];
#pragma unroll
            for (int mt = 0; mt < 2; mt++) {
                int r0 = wm * 32 + mt * 16 + gid;
                aF[mt][0] = __float_as_uint(A[r0 * 36 + kk]);
                aF[mt][1] = __float_as_uint(A[(r0 + 8) * 36 + kk]);
                aF[mt][2] = __float_as_uint(A[r0 * 36 + kk + 4]);
                aF[mt][3] = __float_as_uint(A[(r0 + 8) * 36 + kk + 4]);
            }
            uint32_t bF[8][2];
#pragma unroll
            for (int nt = 0; nt < 8; nt++) {
                int n = wn * 64 + nt * 8 + gid;
                bF[nt][0] = __float_as_uint(B[n * 36 + kk]);
                bF[nt][1] = __float_as_uint(B[n * 36 + kk + 4]);
            }
#pragma unroll
            for (int mt = 0; mt < 2; mt++)
#pragma unroll
                for (int nt = 0; nt < 8; nt++)
                    mma_tf32(acc[mt][nt], aF[mt], bF[nt]);
        }
        __syncthreads();
    }

    // coef partials
    float p[4] = {0.f, 0.f, 0.f, 0.f};
#pragma unroll
    for (int mt = 0; mt < 2; mt++) {
        int r0 = wm * 32 + mt * 16 + gid;
        const float* tg0 = tgt_emb + (size_t)s_trow[r0] * DIM;
        const float* tg1 = tgt_emb + (size_t)s_trow[r0 + 8] * DIM;
#pragma unroll
        for (int nt = 0; nt < 8; nt++) {
            int n = wn * 64 + nt * 8 + tig * 2;
            p[mt * 2 + 0] += tanhf(acc[mt][nt][0]) * __ldg(&tg0[n])
                           + tanhf(acc[mt][nt][1]) * __ldg(&tg0[n + 1]);
            p[mt * 2 + 1] += tanhf(acc[mt][nt][2]) * __ldg(&tg1[n])
                           + tanhf(acc[mt][nt][3]) * __ldg(&tg1[n + 1]);
        }
    }
#pragma unroll
    for (int i = 0; i < 4; i++) {
        p[i] += __shfl_xor_sync(0xffffffffu, p[i], 1);
        p[i] += __shfl_xor_sync(0xffffffffu, p[i], 2);
    }
    if (tig == 0) {
        atomicAdd(&s_coef[wm * 32 + gid], p[0]);
        atomicAdd(&s_coef[wm * 32 + gid + 8], p[1]);
        atomicAdd(&s_coef[wm * 32 + 16 + gid], p[2]);
        atomicAdd(&s_coef[wm * 32 + 16 + gid + 8], p[3]);
    }
    __syncthreads();

    // scatter: select[dst] += coef * ft[src] (full-precision ft)
#pragma unroll
    for (int i = 0; i < 8; i++) {
        int rl = wid * 8 + i;
        float cf = s_coef[rl];
        const float4* fp = (const float4*)(g_ft + (size_t)s_src[rl] * DIM);
        float* op = g_sel + (size_t)s_dst[rl] * DIM;
#pragma unroll
        for (int j = 0; j < 2; j++) {
            int cc = lane + 32 * j;
            float4 v = fp[cc];
            v.x *= cf; v.y *= cf; v.z *= cf; v.w *= cf;
            red_add_v4(op + cc * 4, v);
        }
    }
}

// ---------------- K5: scores = selr @ embr[1:]^T (mma.sync tf32) ------------
// R9 geometry: 128x128 block tile, 256 threads = 8 warps, wm=wid&3, wn=wid>>2.
__global__ __launch_bounds__(256) void k_scores_mma(float* __restrict__ out) {
    extern __shared__ float sm[];
    float* Abuf[2] = {sm, sm + 4608};                 // 128*36 floats each
    float* Bbuf[2] = {sm + 9216, sm + 9216 + 4608};
    int tid = threadIdx.x, lane = tid & 31, wid = tid >> 5;
    int gid = lane >> 2, tig = lane & 3;
    int wm = wid & 3, wn = wid >> 2;
    int n0 = blockIdx.x * 128, m0 = blockIdx.y * 128;

    auto load_chunk = [&](int c, int b) {
        int k0 = c * 32;
#pragma unroll
        for (int it = 0; it < 4; it++) {
            int f = tid + 256 * it;
            int row = f >> 3, c4 = f & 7;
            cp16(s2u(&Abuf[b][row * 36 + c4 * 4]),
                 g_selr + (size_t)(m0 + row) * DIM + k0 + c4 * 4);
        }
#pragma unroll
        for (int it = 0; it < 4; it++) {
            int f = tid + 256 * it;
            int row = f >> 3, c4 = f & 7;
            int gn = n0 + row;
            uint32_t ok = (gn < NOUT) ? 16u : 0u;
            const float* src = g_embr + (size_t)((gn < NOUT) ? gn + 1 : 0) * DIM
                             + k0 + c4 * 4;
            cp16z(s2u(&Bbuf[b][row * 36 + c4 * 4]), src, ok);
        }
        CP_COMMIT();
    };

    float acc[2][8][4];
#pragma unroll
    for (int i = 0; i < 2; i++)
#pragma unroll
        for (int j = 0; j < 8; j++)
#pragma unroll
            for (int q = 0; q < 4; q++) acc[i][j][q] = 0.f;

    load_chunk(0, 0);
    for (int c = 0; c < 8; c++) {
        int b = c & 1;
        if (c + 1 < 8) { load_chunk(c + 1, b ^ 1); CP_WAIT1(); }
        else CP_WAIT0();
        __syncthreads();
        const float* A = Abuf[b];
        const float* B = Bbuf[b];
#pragma unroll
        for (int k8 = 0; k8 < 4; k8++) {
            int kk = k8 * 8 + tig;
            uint32_t aF[2][4];
#pragma unroll
            for (int mt = 0; mt < 2; mt++) {
                int r0 = wm * 32 + mt * 16 + gid;
                aF[mt][0] = __float_as_uint(A[r0 * 36 + kk]);
                aF[mt][1] = __float_as_uint(A[(r0 + 8) * 36 + kk]);
                aF[mt][2] = __float_as_uint(A[r0 * 36 + kk + 4]);
                aF[mt][3] = __float_as_uint(A[(r0 + 8) * 36 + kk + 4]);
            }
            uint32_t bF[8][2];
#pragma unroll
            for (int nt = 0; nt < 8; nt++) {
                int n = wn * 64 + nt * 8 + gid;
                bF[nt][0] = __float_as_uint(B[n * 36 + kk]);
                bF[nt][1] = __float_as_uint(B[n * 36 + kk + 4]);
            }
#pragma unroll
            for (int mt = 0; mt < 2; mt++)
#pragma unroll
                for (int nt = 0; nt < 8; nt++)
                    mma_tf32(acc[mt][nt], aF[mt], bF[nt]);
        }
        __syncthreads();
    }

    // epilogue: direct STG from fragments
#pragma unroll
    for (int mt = 0; mt < 2; mt++) {
        int r0 = m0 + wm * 32 + mt * 16 + gid;
#pragma unroll
        for (int nt = 0; nt < 8; nt++) {
            int n = n0 + wn * 64 + nt * 8 + tig * 2;
            if (n < NOUT) {
                out[(size_t)r0 * NOUT + n] = acc[mt][nt][0];
                out[(size_t)(r0 + 8) * NOUT + n] = acc[mt][nt][2];
                if (n + 1 < NOUT) {
                    out[(size_t)r0 * NOUT + n + 1] = acc[mt][nt][1];
                    out[(size_t)(r0 + 8) * NOUT + n + 1] = acc[mt][nt][3];
                }
            }
        }
    }
}

// ---------------- launch ----------------
extern "C" void kernel_launch(void* const* d_in, const int* in_sizes, int n_in,
                              void* d_out, int out_size) {
    const int* iid = (const int*)d_in[2];
    const int* pid = (const int*)d_in[3];
    const int* tid = (const int*)d_in[4];
    const int* i_src = (const int*)d_in[5];
    const int* i_dst = (const int*)d_in[6];
    const int* agg_src = (const int*)d_in[7];
    const int* agg_dst = (const int*)d_in[8];
    const float* emb = (const float*)d_in[9];
    const float* pos_emb = (const float*)d_in[10];
    const float* tgt_emb = (const float*)d_in[11];
    const float* p_w = (const float*)d_in[12];
    const float* q_w = (const float*)d_in[13];
    float* out = (float*)d_out;

    cudaFuncSetAttribute(k_mid_mma, cudaFuncAttributeMaxDynamicSharedMemorySize,
                         92160);
    cudaFuncSetAttribute(k_scores_mma, cudaFuncAttributeMaxDynamicSharedMemorySize,
                         73728);

    k_zero<<<2048, 256>>>();
    k_round_in<0><<<(NUM_NODE * (DIM / 4) + 255) / 256, 256>>>(
        (const float4*)emb, NUM_NODE * (DIM / 4));
    k_round_in<1><<<(DIM * KDIM / 4 + 255) / 256, 256>>>(
        (const float4*)q_w, DIM * KDIM / 4);
    k_round_in<2><<<(200 * (DIM / 4) + 255) / 256, 256>>>(
        (const float4*)pos_emb, 200 * (DIM / 4));
    k_edge2<<<E_INT / 8, 256>>>(i_src, i_dst, iid, emb, p_w);
    k_norm<<<(N_ITEM * (DIM / 4) + 255) / 256, 256>>>();
    k_mid_mma<<<N_ITEM / 64, 256, 92160>>>(pid, agg_src, agg_dst, tid, tgt_emb);
    k_round_sel<<<(N_TGT * (DIM / 4) + 255) / 256, 256>>>();
    dim3 g5((NOUT + 127) / 128, N_TGT / 128);
    k_scores_mma<<<g5, 256, 73728>>>(out);
}